// round 1
// baseline (speedup 1.0000x reference)
#include <cuda_runtime.h>
#include <cuda_bf16.h>
#include <math.h>

// Problem constants
#define B_   8192
#define P_   4
#define L_   (B_ * P_)
#define V_   100000
#define D_   128
#define NS_  26
#define NE_  (NS_ + 1)            // 27 embedding slots (dense + 26 pooled)
#define NINT ((NE_ * (NE_ - 1)) / 2)   // 351 upper-tri interactions
#define NFEAT (D_ + NINT)         // 479

// ---------------- scratch (no allocations allowed) ----------------
__device__ float g_h1[B_ * 512];
__device__ float g_h2[B_ * 256];
__device__ float g_all[(size_t)B_ * NE_ * D_];   // all_embs: [B][27][128]
__device__ float g_feat[(size_t)B_ * NFEAT];     // [B][479]
__device__ float g_t1[B_ * 512];
__device__ float g_t2[B_ * 256];

// ---------------- embedding bag (sum pooling) ----------------
// one warp per (bag b, table s); D=128 -> 32 float4 lanes
__global__ void embed_kernel(const void* __restrict__ sx_raw,
                             const void* __restrict__ off_raw,
                             const float* __restrict__ tables)
{
    int g = blockIdx.x * blockDim.x + threadIdx.x;
    int warp = g >> 5;
    int lane = g & 31;
    if (warp >= B_ * NS_) return;
    int b = warp / NS_;
    int s = warp - b * NS_;

    const long long* off64 = (const long long*)off_raw;
    const int*       off32 = (const int*)off_raw;
    // offsets = [0,4,8,...]; if stored as int64 then off64[1]==4, else (int32) it's 4|8<<32
    bool is64 = (off64[1] == (long long)P_);

    long long start, end;
    if (is64) {
        start = off64[b];
        end   = (b + 1 < B_) ? off64[b + 1] : (long long)L_;
    } else {
        start = (long long)off32[b];
        end   = (b + 1 < B_) ? (long long)off32[b + 1] : (long long)L_;
    }

    const long long* sx64 = (const long long*)sx_raw;
    const int*       sx32 = (const int*)sx_raw;

    float4 acc = make_float4(0.f, 0.f, 0.f, 0.f);
    for (long long p = start; p < end; ++p) {
        long long idx = is64 ? sx64[p * NS_ + s] : (long long)sx32[p * NS_ + s];
        const float4* row = (const float4*)(tables + ((size_t)s * V_ + (size_t)idx) * D_);
        float4 v = __ldg(&row[lane]);
        acc.x += v.x; acc.y += v.y; acc.z += v.z; acc.w += v.w;
    }
    float4* dst = (float4*)(g_all + ((size_t)b * NE_ + 1 + s) * D_);
    dst[lane] = acc;
}

// ---------------- tiled fp32 GEMM: C = act(A @ W + bias) ----------------
// A: MxK row-major, W: KxN row-major, C row stride = ldc.
// Grid: (N/64, M/64), 256 threads, each thread 4x4 microtile.
#define TIL 64
#define BKK 16
__global__ void gemm_bias_relu(const float* __restrict__ A,
                               const float* __restrict__ W,
                               const float* __restrict__ bias,
                               float* __restrict__ C,
                               int M, int N, int K, int ldc, int do_relu)
{
    __shared__ float As[BKK][TIL + 1];
    __shared__ float Ws[BKK][TIL + 1];
    int bm = blockIdx.y * TIL;
    int bn = blockIdx.x * TIL;
    int tid = threadIdx.x;
    int tx = tid & 15, ty = tid >> 4;

    float acc[4][4] = {};

    for (int k0 = 0; k0 < K; k0 += BKK) {
        #pragma unroll
        for (int i = 0; i < 4; i++) {
            int idx = tid + i * 256;
            int m = idx >> 4;       // / BKK
            int k = idx & 15;
            As[k][m] = (k0 + k < K) ? A[(size_t)(bm + m) * K + k0 + k] : 0.f;
        }
        #pragma unroll
        for (int i = 0; i < 4; i++) {
            int idx = tid + i * 256;
            int k = idx >> 6;       // / TIL
            int n = idx & 63;
            Ws[k][n] = (k0 + k < K) ? W[(size_t)(k0 + k) * N + bn + n] : 0.f;
        }
        __syncthreads();
        #pragma unroll
        for (int kk = 0; kk < BKK; kk++) {
            float a[4], w[4];
            #pragma unroll
            for (int i = 0; i < 4; i++) a[i] = As[kk][ty * 4 + i];
            #pragma unroll
            for (int j = 0; j < 4; j++) w[j] = Ws[kk][tx * 4 + j];
            #pragma unroll
            for (int i = 0; i < 4; i++)
                #pragma unroll
                for (int j = 0; j < 4; j++)
                    acc[i][j] += a[i] * w[j];
        }
        __syncthreads();
    }

    #pragma unroll
    for (int i = 0; i < 4; i++) {
        int row = bm + ty * 4 + i;
        #pragma unroll
        for (int j = 0; j < 4; j++) {
            int col = bn + tx * 4 + j;
            float v = acc[i][j] + bias[col];
            if (do_relu) v = fmaxf(v, 0.f);
            C[(size_t)row * ldc + col] = v;
        }
    }
}

// ---------------- interaction: upper-tri dot products + dense copy ----------------
// one block per batch row; smem 27x128 with stride 129 (bank-conflict-free)
__global__ void interact_kernel(const float* __restrict__ all_embs,
                                float* __restrict__ feat)
{
    __shared__ float e[NE_ * 129];
    int b = blockIdx.x;
    const float* src = all_embs + (size_t)b * NE_ * D_;
    for (int i = threadIdx.x; i < NE_ * D_; i += blockDim.x) {
        int r = i >> 7;       // / 128
        int d = i & 127;
        e[r * 129 + d] = src[i];
    }
    __syncthreads();

    float* out = feat + (size_t)b * NFEAT;
    int t = threadIdx.x;
    if (t < D_) out[t] = e[t];   // dense part = row 0
    if (t < NINT) {
        // map linear t -> (r, c) of triu(27, k=1), row-major
        int r = 0, rem = t;
        while (rem >= (NS_ - r)) { rem -= (NS_ - r); r++; }
        int c = r + 1 + rem;
        const float* er = e + r * 129;
        const float* ec = e + c * 129;
        float sum = 0.f;
        #pragma unroll 8
        for (int d = 0; d < D_; d++) sum += er[d] * ec[d];
        out[D_ + t] = sum;
    }
}

// ---------------- final layer: sigmoid(t2 @ tw3 + tb3) ----------------
// one warp per row; K = 256
__global__ void final_kernel(const float* __restrict__ t2,
                             const float* __restrict__ w,
                             const float* __restrict__ bias,
                             float* __restrict__ out)
{
    int row = blockIdx.x * (blockDim.x >> 5) + (threadIdx.x >> 5);
    int lane = threadIdx.x & 31;
    if (row >= B_) return;
    const float* x = t2 + (size_t)row * 256;
    float s = 0.f;
    #pragma unroll
    for (int i = lane; i < 256; i += 32) s += x[i] * w[i];
    #pragma unroll
    for (int o = 16; o; o >>= 1) s += __shfl_xor_sync(0xFFFFFFFFu, s, o);
    if (lane == 0) out[row] = 1.f / (1.f + expf(-(s + bias[0])));
}

// ---------------- launch ----------------
extern "C" void kernel_launch(void* const* d_in, const int* in_sizes, int n_in,
                              void* d_out, int out_size)
{
    const float* dense_x   = (const float*)d_in[0];
    const void*  sparse_x  = d_in[1];
    const void*  sparse_of = d_in[2];
    const float* tables    = (const float*)d_in[3];
    const float* bw1 = (const float*)d_in[4];
    const float* bb1 = (const float*)d_in[5];
    const float* bw2 = (const float*)d_in[6];
    const float* bb2 = (const float*)d_in[7];
    const float* bw3 = (const float*)d_in[8];
    const float* bb3 = (const float*)d_in[9];
    const float* tw1 = (const float*)d_in[10];
    const float* tb1 = (const float*)d_in[11];
    const float* tw2 = (const float*)d_in[12];
    const float* tb2 = (const float*)d_in[13];
    const float* tw3 = (const float*)d_in[14];
    const float* tb3 = (const float*)d_in[15];
    float* out = (float*)d_out;

    float *h1, *h2, *all, *feat, *t1, *t2;
    cudaGetSymbolAddress((void**)&h1,   g_h1);
    cudaGetSymbolAddress((void**)&h2,   g_h2);
    cudaGetSymbolAddress((void**)&all,  g_all);
    cudaGetSymbolAddress((void**)&feat, g_feat);
    cudaGetSymbolAddress((void**)&t1,   g_t1);
    cudaGetSymbolAddress((void**)&t2,   g_t2);

    // embedding bags -> all_embs slots [1..26]
    {
        int nwarps = B_ * NS_;
        int threads = 256;
        int blocks = (nwarps * 32 + threads - 1) / threads;
        embed_kernel<<<blocks, threads>>>(sparse_x, sparse_of, tables);
    }

    // bottom MLP
    gemm_bias_relu<<<dim3(512 / TIL, B_ / TIL), 256>>>(dense_x, bw1, bb1, h1, B_, 512, 13, 512, 1);
    gemm_bias_relu<<<dim3(256 / TIL, B_ / TIL), 256>>>(h1, bw2, bb2, h2, B_, 256, 512, 256, 1);
    // layer 3 writes directly into all_embs slot 0 (ldc = 27*128)
    gemm_bias_relu<<<dim3(128 / TIL, B_ / TIL), 256>>>(h2, bw3, bb3, all, B_, 128, 256, NE_ * D_, 1);

    // interaction + feature concat
    interact_kernel<<<B_, 384>>>(all, feat);

    // top MLP
    gemm_bias_relu<<<dim3(512 / TIL, B_ / TIL), 256>>>(feat, tw1, tb1, t1, B_, 512, NFEAT, 512, 1);
    gemm_bias_relu<<<dim3(256 / TIL, B_ / TIL), 256>>>(t1, tw2, tb2, t2, B_, 256, 512, 256, 1);

    // final sigmoid layer
    final_kernel<<<B_ / 8, 256>>>(t2, tw3, tb3, out);
}

// round 2
// speedup vs baseline: 1.1685x; 1.1685x over previous
#include <cuda_runtime.h>
#include <cuda_bf16.h>
#include <math.h>
#include <stdint.h>

// Problem constants
#define B_   8192
#define P_   4
#define L_   (B_ * P_)
#define V_   100000
#define D_   128
#define NS_  26
#define NE_  (NS_ + 1)            // 27 embedding slots (dense + 26 pooled)
#define NINT ((NE_ * (NE_ - 1)) / 2)   // 351 upper-tri interactions
#define NFEAT (D_ + NINT)         // 479

// ---------------- scratch (no allocations allowed) ----------------
__device__ float g_h1[B_ * 512];
__device__ float g_h2[B_ * 256];
__device__ float g_all[(size_t)B_ * NE_ * D_];   // all_embs: [B][27][128]
__device__ float g_feat[(size_t)B_ * NFEAT];     // [B][479]
__device__ float g_t1[B_ * 512];
__device__ float g_t2[B_ * 256];

// ---------------- helpers ----------------
__device__ __forceinline__ uint32_t f2tf32(float f) {
    uint32_t r;
    asm("cvt.rna.tf32.f32 %0, %1;" : "=r"(r) : "f"(f));
    return r;
}

__device__ __forceinline__ void mma_tf32(float* c, const uint32_t* a, const uint32_t* b) {
    asm volatile(
        "mma.sync.aligned.m16n8k8.row.col.f32.tf32.tf32.f32 "
        "{%0,%1,%2,%3},{%4,%5,%6,%7},{%8,%9},{%0,%1,%2,%3};"
        : "+f"(c[0]), "+f"(c[1]), "+f"(c[2]), "+f"(c[3])
        : "r"(a[0]), "r"(a[1]), "r"(a[2]), "r"(a[3]), "r"(b[0]), "r"(b[1]));
}

// ---------------- embedding bag (sum pooling) ----------------
// one warp per (bag b, table s); D=128 -> 32 float4 lanes
__global__ void embed_kernel(const void* __restrict__ sx_raw,
                             const void* __restrict__ off_raw,
                             const float* __restrict__ tables)
{
    int g = blockIdx.x * blockDim.x + threadIdx.x;
    int warp = g >> 5;
    int lane = g & 31;
    if (warp >= B_ * NS_) return;
    int b = warp / NS_;
    int s = warp - b * NS_;

    const long long* off64 = (const long long*)off_raw;
    const int*       off32 = (const int*)off_raw;
    bool is64 = (off64[1] == (long long)P_);

    long long start, end;
    if (is64) {
        start = off64[b];
        end   = (b + 1 < B_) ? off64[b + 1] : (long long)L_;
    } else {
        start = (long long)off32[b];
        end   = (b + 1 < B_) ? (long long)off32[b + 1] : (long long)L_;
    }

    const long long* sx64 = (const long long*)sx_raw;
    const int*       sx32 = (const int*)sx_raw;

    float4 acc = make_float4(0.f, 0.f, 0.f, 0.f);
    for (long long p = start; p < end; ++p) {
        long long idx = is64 ? sx64[p * NS_ + s] : (long long)sx32[p * NS_ + s];
        const float4* row = (const float4*)(tables + ((size_t)s * V_ + (size_t)idx) * D_);
        float4 v = __ldg(&row[lane]);
        acc.x += v.x; acc.y += v.y; acc.z += v.z; acc.w += v.w;
    }
    float4* dst = (float4*)(g_all + ((size_t)b * NE_ + 1 + s) * D_);
    dst[lane] = acc;
}

// ---------------- tf32 tensor-core GEMM: C = act(A @ W + bias) ----------------
// A: MxK row-major fp32, W: KxN row-major fp32, C row stride = ldc.
// Tile 128x64x16; 256 threads = 8 warps in 4(m) x 2(n); warp tile 32x32.
// Each warp: 2 m-frags (16) x 4 n-frags (8), mma.m16n8k8.tf32.
#define TBM 128
#define TBN 64
#define TBK 16

__global__ __launch_bounds__(256) void gemm_tf32(
    const float* __restrict__ A,
    const float* __restrict__ W,
    const float* __restrict__ bias,
    float* __restrict__ C,
    int M, int N, int K, int ldc, int do_relu)
{
    __shared__ float As[TBM][20];   // pad 20: conflict-free frag reads, float4-aligned
    __shared__ float Bs[TBK][72];   // pad 72: conflict-free frag reads

    const int tid  = threadIdx.x;
    const int warp = tid >> 5;
    const int lane = tid & 31;
    const int wm   = warp & 3;      // 0..3
    const int wn   = warp >> 2;     // 0..1
    const int g    = lane >> 2;     // group 0..7
    const int t    = lane & 3;      // thread-in-group 0..3

    const int bm = blockIdx.y * TBM;
    const int bn = blockIdx.x * TBN;

    float acc[2][4][4];
    #pragma unroll
    for (int i = 0; i < 2; i++)
        #pragma unroll
        for (int j = 0; j < 4; j++)
            #pragma unroll
            for (int q = 0; q < 4; q++) acc[i][j][q] = 0.f;

    const bool kvec = ((K & 15) == 0);
    const int nk = (K + TBK - 1) / TBK;

    for (int kt = 0; kt < nk; kt++) {
        const int k0 = kt * TBK;

        // ---- load A tile (128x16) ----
        if (kvec) {
            // 512 float4 loads, 2 per thread
            #pragma unroll
            for (int i = 0; i < 2; i++) {
                int idx = tid + i * 256;
                int row = idx >> 2;
                int c4  = (idx & 3) * 4;
                const float4* src = (const float4*)(A + (size_t)(bm + row) * K + k0 + c4);
                float4 v = *src;
                As[row][c4 + 0] = __uint_as_float(f2tf32(v.x));
                As[row][c4 + 1] = __uint_as_float(f2tf32(v.y));
                As[row][c4 + 2] = __uint_as_float(f2tf32(v.z));
                As[row][c4 + 3] = __uint_as_float(f2tf32(v.w));
            }
        } else {
            #pragma unroll
            for (int i = 0; i < 8; i++) {
                int idx = tid + i * 256;
                int row = idx >> 4;
                int col = idx & 15;
                float v = (k0 + col < K) ? A[(size_t)(bm + row) * K + k0 + col] : 0.f;
                As[row][col] = __uint_as_float(f2tf32(v));
            }
        }

        // ---- load B tile (16x64), one float4 per thread ----
        {
            int krow = tid >> 4;        // 0..15
            int c4   = (tid & 15) * 4;  // 0..60
            float4 v = make_float4(0.f, 0.f, 0.f, 0.f);
            if (k0 + krow < K)
                v = *(const float4*)(W + (size_t)(k0 + krow) * N + bn + c4);
            Bs[krow][c4 + 0] = __uint_as_float(f2tf32(v.x));
            Bs[krow][c4 + 1] = __uint_as_float(f2tf32(v.y));
            Bs[krow][c4 + 2] = __uint_as_float(f2tf32(v.z));
            Bs[krow][c4 + 3] = __uint_as_float(f2tf32(v.w));
        }
        __syncthreads();

        // ---- compute: 2 k-steps of 8 ----
        #pragma unroll
        for (int ks = 0; ks < 2; ks++) {
            uint32_t a[2][4];
            #pragma unroll
            for (int fm = 0; fm < 2; fm++) {
                int row = wm * 32 + fm * 16 + g;
                int kc  = ks * 8 + t;
                a[fm][0] = __float_as_uint(As[row    ][kc    ]);
                a[fm][1] = __float_as_uint(As[row + 8][kc    ]);
                a[fm][2] = __float_as_uint(As[row    ][kc + 4]);
                a[fm][3] = __float_as_uint(As[row + 8][kc + 4]);
            }
            uint32_t b[4][2];
            #pragma unroll
            for (int fn = 0; fn < 4; fn++) {
                int n  = wn * 32 + fn * 8 + g;
                int kc = ks * 8 + t;
                b[fn][0] = __float_as_uint(Bs[kc    ][n]);
                b[fn][1] = __float_as_uint(Bs[kc + 4][n]);
            }
            #pragma unroll
            for (int fm = 0; fm < 2; fm++)
                #pragma unroll
                for (int fn = 0; fn < 4; fn++)
                    mma_tf32(acc[fm][fn], a[fm], b[fn]);
        }
        __syncthreads();
    }

    // ---- epilogue: bias + optional relu ----
    #pragma unroll
    for (int fm = 0; fm < 2; fm++) {
        int row0 = bm + wm * 32 + fm * 16 + g;
        #pragma unroll
        for (int fn = 0; fn < 4; fn++) {
            int col0 = bn + wn * 32 + fn * 8 + 2 * t;
            float bv0 = bias[col0], bv1 = bias[col0 + 1];
            float v0 = acc[fm][fn][0] + bv0;
            float v1 = acc[fm][fn][1] + bv1;
            float v2 = acc[fm][fn][2] + bv0;
            float v3 = acc[fm][fn][3] + bv1;
            if (do_relu) {
                v0 = fmaxf(v0, 0.f); v1 = fmaxf(v1, 0.f);
                v2 = fmaxf(v2, 0.f); v3 = fmaxf(v3, 0.f);
            }
            C[(size_t)row0 * ldc + col0]           = v0;
            C[(size_t)row0 * ldc + col0 + 1]       = v1;
            C[(size_t)(row0 + 8) * ldc + col0]     = v2;
            C[(size_t)(row0 + 8) * ldc + col0 + 1] = v3;
        }
    }
}

// ---------------- interaction: upper-tri dot products + dense copy ----------------
__global__ void interact_kernel(const float* __restrict__ all_embs,
                                float* __restrict__ feat)
{
    __shared__ float e[NE_ * 129];
    int b = blockIdx.x;
    const float* src = all_embs + (size_t)b * NE_ * D_;
    for (int i = threadIdx.x; i < NE_ * D_; i += blockDim.x) {
        int r = i >> 7;
        int d = i & 127;
        e[r * 129 + d] = src[i];
    }
    __syncthreads();

    float* out = feat + (size_t)b * NFEAT;
    int t = threadIdx.x;
    if (t < D_) out[t] = e[t];
    if (t < NINT) {
        int r = 0, rem = t;
        while (rem >= (NS_ - r)) { rem -= (NS_ - r); r++; }
        int c = r + 1 + rem;
        const float* er = e + r * 129;
        const float* ec = e + c * 129;
        float sum = 0.f;
        #pragma unroll 8
        for (int d = 0; d < D_; d++) sum += er[d] * ec[d];
        out[D_ + t] = sum;
    }
}

// ---------------- final layer: sigmoid(t2 @ tw3 + tb3) ----------------
__global__ void final_kernel(const float* __restrict__ t2,
                             const float* __restrict__ w,
                             const float* __restrict__ bias,
                             float* __restrict__ out)
{
    int row = blockIdx.x * (blockDim.x >> 5) + (threadIdx.x >> 5);
    int lane = threadIdx.x & 31;
    if (row >= B_) return;
    const float* x = t2 + (size_t)row * 256;
    float s = 0.f;
    #pragma unroll
    for (int i = lane; i < 256; i += 32) s += x[i] * w[i];
    #pragma unroll
    for (int o = 16; o; o >>= 1) s += __shfl_xor_sync(0xFFFFFFFFu, s, o);
    if (lane == 0) out[row] = 1.f / (1.f + expf(-(s + bias[0])));
}

// ---------------- launch ----------------
extern "C" void kernel_launch(void* const* d_in, const int* in_sizes, int n_in,
                              void* d_out, int out_size)
{
    const float* dense_x   = (const float*)d_in[0];
    const void*  sparse_x  = d_in[1];
    const void*  sparse_of = d_in[2];
    const float* tables    = (const float*)d_in[3];
    const float* bw1 = (const float*)d_in[4];
    const float* bb1 = (const float*)d_in[5];
    const float* bw2 = (const float*)d_in[6];
    const float* bb2 = (const float*)d_in[7];
    const float* bw3 = (const float*)d_in[8];
    const float* bb3 = (const float*)d_in[9];
    const float* tw1 = (const float*)d_in[10];
    const float* tb1 = (const float*)d_in[11];
    const float* tw2 = (const float*)d_in[12];
    const float* tb2 = (const float*)d_in[13];
    const float* tw3 = (const float*)d_in[14];
    const float* tb3 = (const float*)d_in[15];
    float* out = (float*)d_out;

    float *h1, *h2, *all, *feat, *t1, *t2;
    cudaGetSymbolAddress((void**)&h1,   g_h1);
    cudaGetSymbolAddress((void**)&h2,   g_h2);
    cudaGetSymbolAddress((void**)&all,  g_all);
    cudaGetSymbolAddress((void**)&feat, g_feat);
    cudaGetSymbolAddress((void**)&t1,   g_t1);
    cudaGetSymbolAddress((void**)&t2,   g_t2);

    // embedding bags -> all_embs slots [1..26]
    {
        int nwarps = B_ * NS_;
        int threads = 256;
        int blocks = (nwarps * 32 + threads - 1) / threads;
        embed_kernel<<<blocks, threads>>>(sparse_x, sparse_of, tables);
    }

    // bottom MLP (tf32 tensor cores)
    gemm_tf32<<<dim3(512 / TBN, B_ / TBM), 256>>>(dense_x, bw1, bb1, h1, B_, 512, 13, 512, 1);
    gemm_tf32<<<dim3(256 / TBN, B_ / TBM), 256>>>(h1, bw2, bb2, h2, B_, 256, 512, 256, 1);
    // layer 3 writes directly into all_embs slot 0 (ldc = 27*128)
    gemm_tf32<<<dim3(128 / TBN, B_ / TBM), 256>>>(h2, bw3, bb3, all, B_, 128, 256, NE_ * D_, 1);

    // interaction + feature concat
    interact_kernel<<<B_, 384>>>(all, feat);

    // top MLP (tf32 tensor cores)
    gemm_tf32<<<dim3(512 / TBN, B_ / TBM), 256>>>(feat, tw1, tb1, t1, B_, 512, NFEAT, 512, 1);
    gemm_tf32<<<dim3(256 / TBN, B_ / TBM), 256>>>(t1, tw2, tb2, t2, B_, 256, 512, 256, 1);

    // final sigmoid layer
    final_kernel<<<B_ / 8, 256>>>(t2, tw3, tb3, out);
}

// round 3
// speedup vs baseline: 1.9478x; 1.6669x over previous
#include <cuda_runtime.h>
#include <cuda_bf16.h>
#include <math.h>
#include <stdint.h>

// Problem constants
#define B_   8192
#define P_   4
#define L_   (B_ * P_)
#define V_   100000
#define D_   128
#define NS_  26
#define NE_  (NS_ + 1)            // 27 embedding slots (dense + 26 pooled)
#define NINT ((NE_ * (NE_ - 1)) / 2)   // 351
#define NFEAT (D_ + NINT)         // 479
#define NFEATP 480                // padded feature stride (col 479 zeroed)

// ---------------- scratch (no allocations allowed) ----------------
__device__ float g_h1[B_ * 512];
__device__ float g_h2[B_ * 256];
__device__ float g_all[(size_t)B_ * NE_ * D_];   // all_embs: [B][27][128]
__device__ float g_feat[(size_t)B_ * NFEATP];    // [B][480]
__device__ float g_t1[B_ * 512];
__device__ float g_t2[B_ * 256];

// ---------------- helpers ----------------
__device__ __forceinline__ uint32_t pack_bf16(float a, float b) {
    __nv_bfloat162 h = __floats2bfloat162_rn(a, b);
    return *reinterpret_cast<uint32_t*>(&h);
}

__device__ __forceinline__ void ldsm4(uint32_t& r0, uint32_t& r1, uint32_t& r2, uint32_t& r3,
                                      uint32_t saddr) {
    asm volatile("ldmatrix.sync.aligned.m8n8.x4.shared.b16 {%0,%1,%2,%3}, [%4];"
                 : "=r"(r0), "=r"(r1), "=r"(r2), "=r"(r3) : "r"(saddr));
}
__device__ __forceinline__ void ldsm4t(uint32_t& r0, uint32_t& r1, uint32_t& r2, uint32_t& r3,
                                       uint32_t saddr) {
    asm volatile("ldmatrix.sync.aligned.m8n8.x4.trans.shared.b16 {%0,%1,%2,%3}, [%4];"
                 : "=r"(r0), "=r"(r1), "=r"(r2), "=r"(r3) : "r"(saddr));
}
__device__ __forceinline__ void mma_bf16(float* c, const uint32_t* a, const uint32_t* b) {
    asm volatile(
        "mma.sync.aligned.m16n8k16.row.col.f32.bf16.bf16.f32 "
        "{%0,%1,%2,%3},{%4,%5,%6,%7},{%8,%9},{%0,%1,%2,%3};"
        : "+f"(c[0]), "+f"(c[1]), "+f"(c[2]), "+f"(c[3])
        : "r"(a[0]), "r"(a[1]), "r"(a[2]), "r"(a[3]), "r"(b[0]), "r"(b[1]));
}

// ---------------- embedding bag (sum pooling) ----------------
// one warp per (bag b, table s); D=128 -> 32 float4 lanes
__global__ void embed_kernel(const void* __restrict__ sx_raw,
                             const void* __restrict__ off_raw,
                             const float* __restrict__ tables)
{
    int g = blockIdx.x * blockDim.x + threadIdx.x;
    int warp = g >> 5;
    int lane = g & 31;
    if (warp >= B_ * NS_) return;
    int b = warp / NS_;
    int s = warp - b * NS_;

    const long long* off64 = (const long long*)off_raw;
    const int*       off32 = (const int*)off_raw;
    bool is64 = (off64[1] == (long long)P_);

    long long start, end;
    if (is64) {
        start = off64[b];
        end   = (b + 1 < B_) ? off64[b + 1] : (long long)L_;
    } else {
        start = (long long)off32[b];
        end   = (b + 1 < B_) ? (long long)off32[b + 1] : (long long)L_;
    }

    const long long* sx64 = (const long long*)sx_raw;
    const int*       sx32 = (const int*)sx_raw;

    float4 acc = make_float4(0.f, 0.f, 0.f, 0.f);
    for (long long p = start; p < end; ++p) {
        long long idx = is64 ? sx64[p * NS_ + s] : (long long)sx32[p * NS_ + s];
        const float4* row = (const float4*)(tables + ((size_t)s * V_ + (size_t)idx) * D_);
        float4 v = __ldg(&row[lane]);
        acc.x += v.x; acc.y += v.y; acc.z += v.z; acc.w += v.w;
    }
    float4* dst = (float4*)(g_all + ((size_t)b * NE_ + 1 + s) * D_);
    dst[lane] = acc;
}

// ---------------- bf16 tensor-core GEMM: C = act(A @ W + bias) ----------------
// A: M x K fp32, row stride lda. W: K x N fp32 row-major. C fp32, row stride ldc.
// fp32 inputs converted to bf16 in the smem fill; fp32 accumulation.
// Tile 128x64x32; 256 thr = 8 warps (4m x 2n); warp tile 32x32.
#define TBM 128
#define TBN 64
#define TBK 32
#define APAD 40   // As row = 40 bf16 = 80B (16B aligned, LDSM conflict-free)
#define BPAD 72   // Bs row = 72 bf16 = 144B (16B aligned, LDSM conflict-free)

__global__ __launch_bounds__(256, 2) void gemm_bf16(
    const float* __restrict__ A,
    const float* __restrict__ W,
    const float* __restrict__ bias,
    float* __restrict__ C,
    int M, int N, int K, int lda, int ldc, int do_relu)
{
    __shared__ alignas(16) unsigned short As[TBM][APAD];
    __shared__ alignas(16) unsigned short Bs[TBK][BPAD];

    const int tid  = threadIdx.x;
    const int warp = tid >> 5;
    const int lane = tid & 31;
    const int wm   = warp & 3;      // 0..3 (m)
    const int wn   = warp >> 2;     // 0..1 (n)
    const int g    = lane >> 2;     // 0..7
    const int t    = lane & 3;      // 0..3

    const int bm = blockIdx.y * TBM;
    const int bn = blockIdx.x * TBN;

    uint32_t sAs = (uint32_t)__cvta_generic_to_shared(&As[0][0]);
    uint32_t sBs = (uint32_t)__cvta_generic_to_shared(&Bs[0][0]);

    float acc[2][4][4];
    #pragma unroll
    for (int i = 0; i < 2; i++)
        #pragma unroll
        for (int j = 0; j < 4; j++)
            #pragma unroll
            for (int q = 0; q < 4; q++) acc[i][j][q] = 0.f;

    const int nk = (K + TBK - 1) / TBK;

    for (int kt = 0; kt < nk; kt++) {
        const int k0 = kt * TBK;

        // ---- A tile 128x32 -> bf16 smem ----
        if ((lda % 4 == 0) && (k0 + TBK <= lda)) {
            #pragma unroll
            for (int i = 0; i < 4; i++) {
                int idx = tid + i * 256;        // 0..1023
                int row = idx >> 3;
                int c4  = (idx & 7) * 4;
                float4 v = *(const float4*)(A + (size_t)(bm + row) * lda + k0 + c4);
                uint32_t* dst = (uint32_t*)&As[row][c4];
                dst[0] = pack_bf16(v.x, v.y);
                dst[1] = pack_bf16(v.z, v.w);
            }
        } else {
            #pragma unroll
            for (int i = 0; i < 8; i++) {
                int idx = tid + i * 256;        // 0..2047, pairs of cols
                int row = idx >> 4;
                int c2  = (idx & 15) * 2;
                float v0 = (k0 + c2     < K) ? A[(size_t)(bm + row) * lda + k0 + c2]     : 0.f;
                float v1 = (k0 + c2 + 1 < K) ? A[(size_t)(bm + row) * lda + k0 + c2 + 1] : 0.f;
                *(uint32_t*)&As[row][c2] = pack_bf16(v0, v1);
            }
        }

        // ---- B tile 32x64 -> bf16 smem (row k guard) ----
        #pragma unroll
        for (int i = 0; i < 2; i++) {
            int idx  = tid + i * 256;           // 0..511
            int krow = idx >> 4;
            int c4   = (idx & 15) * 4;
            float4 v = make_float4(0.f, 0.f, 0.f, 0.f);
            if (k0 + krow < K)
                v = *(const float4*)(W + (size_t)(k0 + krow) * N + bn + c4);
            uint32_t* dst = (uint32_t*)&Bs[krow][c4];
            dst[0] = pack_bf16(v.x, v.y);
            dst[1] = pack_bf16(v.z, v.w);
        }
        __syncthreads();

        // ---- compute: 2 k-steps of 16 ----
        #pragma unroll
        for (int ks = 0; ks < 2; ks++) {
            const int kk = ks * 16;
            uint32_t a[2][4];
            #pragma unroll
            for (int fm = 0; fm < 2; fm++) {
                int row = wm * 32 + fm * 16 + (lane & 15);
                uint32_t addr = sAs + (uint32_t)(row * APAD + kk + (lane >> 4) * 8) * 2u;
                ldsm4(a[fm][0], a[fm][1], a[fm][2], a[fm][3], addr);
            }
            uint32_t b[4][2];
            #pragma unroll
            for (int fn2 = 0; fn2 < 2; fn2++) {
                int krow = kk + (lane & 15);
                int ncol = wn * 32 + fn2 * 16 + (lane >> 4) * 8;
                uint32_t addr = sBs + (uint32_t)(krow * BPAD + ncol) * 2u;
                uint32_t r0, r1, r2, r3;
                ldsm4t(r0, r1, r2, r3, addr);
                b[fn2 * 2][0] = r0; b[fn2 * 2][1] = r1;
                b[fn2 * 2 + 1][0] = r2; b[fn2 * 2 + 1][1] = r3;
            }
            #pragma unroll
            for (int fm = 0; fm < 2; fm++)
                #pragma unroll
                for (int fn = 0; fn < 4; fn++)
                    mma_bf16(acc[fm][fn], a[fm], b[fn]);
        }
        __syncthreads();
    }

    // ---- epilogue: bias + optional relu, fp32 out ----
    #pragma unroll
    for (int fm = 0; fm < 2; fm++) {
        int row0 = bm + wm * 32 + fm * 16 + g;
        #pragma unroll
        for (int fn = 0; fn < 4; fn++) {
            int col0 = bn + wn * 32 + fn * 8 + 2 * t;
            float bv0 = bias[col0], bv1 = bias[col0 + 1];
            float v0 = acc[fm][fn][0] + bv0;
            float v1 = acc[fm][fn][1] + bv1;
            float v2 = acc[fm][fn][2] + bv0;
            float v3 = acc[fm][fn][3] + bv1;
            if (do_relu) {
                v0 = fmaxf(v0, 0.f); v1 = fmaxf(v1, 0.f);
                v2 = fmaxf(v2, 0.f); v3 = fmaxf(v3, 0.f);
            }
            C[(size_t)row0 * ldc + col0]           = v0;
            C[(size_t)row0 * ldc + col0 + 1]       = v1;
            C[(size_t)(row0 + 8) * ldc + col0]     = v2;
            C[(size_t)(row0 + 8) * ldc + col0 + 1] = v3;
        }
    }
}

// ---------------- interaction: upper-tri dot products + dense copy ----------------
__global__ void interact_kernel(const float* __restrict__ all_embs,
                                float* __restrict__ feat)
{
    __shared__ float e[NE_ * 129];
    int b = blockIdx.x;
    const float* src = all_embs + (size_t)b * NE_ * D_;
    for (int i = threadIdx.x; i < NE_ * D_; i += blockDim.x) {
        int r = i >> 7;
        int d = i & 127;
        e[r * 129 + d] = src[i];
    }
    __syncthreads();

    float* out = feat + (size_t)b * NFEATP;
    int t = threadIdx.x;
    if (t < D_) out[t] = e[t];
    if (t < NINT) {
        int r = 0, rem = t;
        while (rem >= (NS_ - r)) { rem -= (NS_ - r); r++; }
        int c = r + 1 + rem;
        const float* er = e + r * 129;
        const float* ec = e + c * 129;
        float sum = 0.f;
        #pragma unroll 8
        for (int d = 0; d < D_; d++) sum += er[d] * ec[d];
        out[D_ + t] = sum;
    }
    if (t == NINT) out[D_ + NINT] = 0.f;   // zero pad col 479
}

// ---------------- final layer: sigmoid(t2 @ tw3 + tb3) ----------------
__global__ void final_kernel(const float* __restrict__ t2,
                             const float* __restrict__ w,
                             const float* __restrict__ bias,
                             float* __restrict__ out)
{
    int row = blockIdx.x * (blockDim.x >> 5) + (threadIdx.x >> 5);
    int lane = threadIdx.x & 31;
    if (row >= B_) return;
    const float* x = t2 + (size_t)row * 256;
    float s = 0.f;
    #pragma unroll
    for (int i = lane; i < 256; i += 32) s += x[i] * w[i];
    #pragma unroll
    for (int o = 16; o; o >>= 1) s += __shfl_xor_sync(0xFFFFFFFFu, s, o);
    if (lane == 0) out[row] = 1.f / (1.f + expf(-(s + bias[0])));
}

// ---------------- launch ----------------
extern "C" void kernel_launch(void* const* d_in, const int* in_sizes, int n_in,
                              void* d_out, int out_size)
{
    const float* dense_x   = (const float*)d_in[0];
    const void*  sparse_x  = d_in[1];
    const void*  sparse_of = d_in[2];
    const float* tables    = (const float*)d_in[3];
    const float* bw1 = (const float*)d_in[4];
    const float* bb1 = (const float*)d_in[5];
    const float* bw2 = (const float*)d_in[6];
    const float* bb2 = (const float*)d_in[7];
    const float* bw3 = (const float*)d_in[8];
    const float* bb3 = (const float*)d_in[9];
    const float* tw1 = (const float*)d_in[10];
    const float* tb1 = (const float*)d_in[11];
    const float* tw2 = (const float*)d_in[12];
    const float* tb2 = (const float*)d_in[13];
    const float* tw3 = (const float*)d_in[14];
    const float* tb3 = (const float*)d_in[15];
    float* out = (float*)d_out;

    float *h1, *h2, *all, *feat, *t1, *t2;
    cudaGetSymbolAddress((void**)&h1,   g_h1);
    cudaGetSymbolAddress((void**)&h2,   g_h2);
    cudaGetSymbolAddress((void**)&all,  g_all);
    cudaGetSymbolAddress((void**)&feat, g_feat);
    cudaGetSymbolAddress((void**)&t1,   g_t1);
    cudaGetSymbolAddress((void**)&t2,   g_t2);

    // embedding bags -> all_embs slots [1..26]
    {
        int nwarps = B_ * NS_;
        int threads = 256;
        int blocks = (nwarps * 32 + threads - 1) / threads;
        embed_kernel<<<blocks, threads>>>(sparse_x, sparse_of, tables);
    }

    // bottom MLP (bf16 tensor cores, fp32 accumulate)
    gemm_bf16<<<dim3(512 / TBN, B_ / TBM), 256>>>(dense_x, bw1, bb1, h1, B_, 512, 13, 13, 512, 1);
    gemm_bf16<<<dim3(256 / TBN, B_ / TBM), 256>>>(h1, bw2, bb2, h2, B_, 256, 512, 512, 256, 1);
    // layer 3 writes directly into all_embs slot 0 (ldc = 27*128)
    gemm_bf16<<<dim3(128 / TBN, B_ / TBM), 256>>>(h2, bw3, bb3, all, B_, 128, 256, 256, NE_ * D_, 1);

    // interaction + feature concat (padded stride 480)
    interact_kernel<<<B_, 384>>>(all, feat);

    // top MLP
    gemm_bf16<<<dim3(512 / TBN, B_ / TBM), 256>>>(feat, tw1, tb1, t1, B_, 512, NFEAT, NFEATP, 512, 1);
    gemm_bf16<<<dim3(256 / TBN, B_ / TBM), 256>>>(t1, tw2, tb2, t2, B_, 256, 512, 512, 256, 1);

    // final sigmoid layer
    final_kernel<<<B_ / 8, 256>>>(t2, tw3, tb3, out);
}

// round 4
// speedup vs baseline: 3.0781x; 1.5803x over previous
#include <cuda_runtime.h>
#include <cuda_bf16.h>
#include <math.h>
#include <stdint.h>

// Problem constants
#define B_   8192
#define P_   4
#define L_   (B_ * P_)
#define V_   100000
#define D_   128
#define NS_  26
#define NE_  (NS_ + 1)            // 27 embedding slots
#define NINT ((NE_ * (NE_ - 1)) / 2)   // 351
#define NFEAT (D_ + NINT)         // 479
#define NFEATP 480                // padded feature stride

typedef __nv_bfloat16 bf16;

// ---------------- scratch (bf16 activations) ----------------
__device__ bf16 g_h1b[(size_t)B_ * 512];
__device__ bf16 g_h2b[(size_t)B_ * 256];
__device__ bf16 g_allb[(size_t)B_ * NE_ * D_];   // [B][27][128]
__device__ bf16 g_featb[(size_t)B_ * NFEATP];    // [B][480]
__device__ bf16 g_t1b[(size_t)B_ * 512];
__device__ bf16 g_t2b[(size_t)B_ * 256];
// bf16 weight copies (K padded to %32)
__device__ bf16 g_wb2[512 * 256];
__device__ bf16 g_wb3[256 * 128];
__device__ bf16 g_wt1[480 * 512];   // row 479 zeroed
__device__ bf16 g_wt2[512 * 256];

// ---------------- helpers ----------------
__device__ __forceinline__ uint32_t pack_bf16(float a, float b) {
    __nv_bfloat162 h = __floats2bfloat162_rn(a, b);
    return *reinterpret_cast<uint32_t*>(&h);
}
__device__ __forceinline__ void ldsm4(uint32_t& r0, uint32_t& r1, uint32_t& r2, uint32_t& r3,
                                      uint32_t saddr) {
    asm volatile("ldmatrix.sync.aligned.m8n8.x4.shared.b16 {%0,%1,%2,%3}, [%4];"
                 : "=r"(r0), "=r"(r1), "=r"(r2), "=r"(r3) : "r"(saddr));
}
__device__ __forceinline__ void ldsm4t(uint32_t& r0, uint32_t& r1, uint32_t& r2, uint32_t& r3,
                                       uint32_t saddr) {
    asm volatile("ldmatrix.sync.aligned.m8n8.x4.trans.shared.b16 {%0,%1,%2,%3}, [%4];"
                 : "=r"(r0), "=r"(r1), "=r"(r2), "=r"(r3) : "r"(saddr));
}
__device__ __forceinline__ void mma_bf16(float* c, const uint32_t* a, const uint32_t* b) {
    asm volatile(
        "mma.sync.aligned.m16n8k16.row.col.f32.bf16.bf16.f32 "
        "{%0,%1,%2,%3},{%4,%5,%6,%7},{%8,%9},{%0,%1,%2,%3};"
        : "+f"(c[0]), "+f"(c[1]), "+f"(c[2]), "+f"(c[3])
        : "r"(a[0]), "r"(a[1]), "r"(a[2]), "r"(a[3]), "r"(b[0]), "r"(b[1]));
}
__device__ __forceinline__ void cpasync16(uint32_t dst, const void* src) {
    asm volatile("cp.async.cg.shared.global [%0], [%1], 16;" :: "r"(dst), "l"(src));
}

// ---------------- weight prep: fp32 -> bf16 (K padded) ----------------
__global__ void prep_weights(const float* __restrict__ bw2, const float* __restrict__ bw3,
                             const float* __restrict__ tw1, const float* __restrict__ tw2)
{
    const int S0 = 512 * 256;            // wb2
    const int S1 = S0 + 256 * 128;       // wb3
    const int S2 = S1 + 480 * 512;       // wt1 (padded)
    const int S3 = S2 + 512 * 256;       // wt2
    for (int i = blockIdx.x * blockDim.x + threadIdx.x; i < S3; i += gridDim.x * blockDim.x) {
        if (i < S0) {
            g_wb2[i] = __float2bfloat16(bw2[i]);
        } else if (i < S1) {
            int j = i - S0;
            g_wb3[j] = __float2bfloat16(bw3[j]);
        } else if (i < S2) {
            int j = i - S1;
            int k = j >> 9;   // /512
            g_wt1[j] = (k < NFEAT) ? __float2bfloat16(tw1[j]) : __float2bfloat16(0.f);
        } else {
            int j = i - S2;
            g_wt2[j] = __float2bfloat16(tw2[j]);
        }
    }
}

// ---------------- embedding bag (sum pooling) -> bf16 ----------------
__global__ void embed_kernel(const void* __restrict__ sx_raw,
                             const void* __restrict__ off_raw,
                             const float* __restrict__ tables)
{
    int g = blockIdx.x * blockDim.x + threadIdx.x;
    int warp = g >> 5;
    int lane = g & 31;
    if (warp >= B_ * NS_) return;
    int b = warp / NS_;
    int s = warp - b * NS_;

    const long long* off64 = (const long long*)off_raw;
    const int*       off32 = (const int*)off_raw;
    bool is64 = (off64[1] == (long long)P_);

    long long start, end;
    if (is64) {
        start = off64[b];
        end   = (b + 1 < B_) ? off64[b + 1] : (long long)L_;
    } else {
        start = (long long)off32[b];
        end   = (b + 1 < B_) ? (long long)off32[b + 1] : (long long)L_;
    }

    const long long* sx64 = (const long long*)sx_raw;
    const int*       sx32 = (const int*)sx_raw;

    float4 acc = make_float4(0.f, 0.f, 0.f, 0.f);
    for (long long p = start; p < end; ++p) {
        long long idx = is64 ? sx64[p * NS_ + s] : (long long)sx32[p * NS_ + s];
        const float4* row = (const float4*)(tables + ((size_t)s * V_ + (size_t)idx) * D_);
        float4 v = __ldg(&row[lane]);
        acc.x += v.x; acc.y += v.y; acc.z += v.z; acc.w += v.w;
    }
    uint2 val;
    val.x = pack_bf16(acc.x, acc.y);
    val.y = pack_bf16(acc.z, acc.w);
    *(uint2*)&g_allb[((size_t)b * NE_ + 1 + s) * D_ + lane * 4] = val;
}

// ---------------- layer1: dense_x(13) -> 512, fp32 FFMA, bf16 out ----------------
__global__ __launch_bounds__(256) void layer1_kernel(const float* __restrict__ X,
                                                     const float* __restrict__ W,
                                                     const float* __restrict__ bias)
{
    __shared__ float As[16][13];
    int m0 = blockIdx.x * 16;
    int tid = threadIdx.x;
    if (tid < 16 * 13) As[tid / 13][tid % 13] = X[(size_t)(m0 + tid / 13) * 13 + tid % 13];
    __syncthreads();

    int n0 = tid * 2;
    float w0[13], w1[13];
    #pragma unroll
    for (int k = 0; k < 13; k++) {
        w0[k] = W[k * 512 + n0];
        w1[k] = W[k * 512 + n0 + 1];
    }
    float b0 = bias[n0], b1 = bias[n0 + 1];
    #pragma unroll 4
    for (int r = 0; r < 16; r++) {
        float s0 = b0, s1 = b1;
        #pragma unroll
        for (int k = 0; k < 13; k++) {
            float a = As[r][k];
            s0 += a * w0[k];
            s1 += a * w1[k];
        }
        s0 = fmaxf(s0, 0.f); s1 = fmaxf(s1, 0.f);
        *(uint32_t*)&g_h1b[(size_t)(m0 + r) * 512 + n0] = pack_bf16(s0, s1);
    }
}

// ---------------- bf16 GEMM with cp.async double buffering ----------------
// A: M x K bf16 (lda), W: K x N bf16 row-major, C: bf16 (ldc). K % 32 == 0,
// M % 128 == 0, N % 64 == 0, lda % 8 == 0, N % 8 == 0.
#define TBM 128
#define TBN 64
#define TBK 32
#define APAD 40   // 80B row stride (16B aligned, LDSM conflict-free)
#define BPAD 72   // 144B row stride

__global__ __launch_bounds__(256, 2) void gemm_bf16a(
    const bf16* __restrict__ A,
    const bf16* __restrict__ W,
    const float* __restrict__ bias,
    bf16* __restrict__ C,
    int N, int K, int lda, int ldc, int do_relu)
{
    __shared__ alignas(16) unsigned short As[2][TBM][APAD];
    __shared__ alignas(16) unsigned short Bs[2][TBK][BPAD];

    const int tid  = threadIdx.x;
    const int warp = tid >> 5;
    const int lane = tid & 31;
    const int wm   = warp & 3;
    const int wn   = warp >> 2;
    const int g    = lane >> 2;
    const int t    = lane & 3;

    const int bm = blockIdx.y * TBM;
    const int bn = blockIdx.x * TBN;

    uint32_t sA = (uint32_t)__cvta_generic_to_shared(&As[0][0][0]);
    uint32_t sB = (uint32_t)__cvta_generic_to_shared(&Bs[0][0][0]);
    const uint32_t ASTAGE = TBM * APAD * 2;
    const uint32_t BSTAGE = TBK * BPAD * 2;

    float acc[2][4][4];
    #pragma unroll
    for (int i = 0; i < 2; i++)
        #pragma unroll
        for (int j = 0; j < 4; j++)
            #pragma unroll
            for (int q = 0; q < 4; q++) acc[i][j][q] = 0.f;

    const int nk = K / TBK;

    // row/chunk mapping for async copies
    const int arow0 = tid >> 2;              // A: chunks tid, tid+256
    const int ac80  = (tid & 3) * 8;
    const int brow  = tid >> 3;              // B: one chunk per thread
    const int bc8   = (tid & 7) * 8;

    #define PREFETCH(KT, BUF)                                                        \
    {                                                                                \
        int k0 = (KT) * TBK;                                                         \
        cpasync16(sA + (BUF) * ASTAGE + (uint32_t)(arow0 * APAD + ac80) * 2,         \
                  A + (size_t)(bm + arow0) * lda + k0 + ac80);                       \
        cpasync16(sA + (BUF) * ASTAGE + (uint32_t)((arow0 + 64) * APAD + ac80) * 2,  \
                  A + (size_t)(bm + arow0 + 64) * lda + k0 + ac80);                  \
        cpasync16(sB + (BUF) * BSTAGE + (uint32_t)(brow * BPAD + bc8) * 2,           \
                  W + (size_t)(k0 + brow) * N + bn + bc8);                           \
        asm volatile("cp.async.commit_group;" ::: "memory");                         \
    }

    PREFETCH(0, 0);

    for (int kt = 0; kt < nk; kt++) {
        if (kt + 1 < nk) {
            PREFETCH(kt + 1, (kt + 1) & 1);
            asm volatile("cp.async.wait_group 1;" ::: "memory");
        } else {
            asm volatile("cp.async.wait_group 0;" ::: "memory");
        }
        __syncthreads();

        uint32_t aBase = sA + (kt & 1) * ASTAGE;
        uint32_t bBase = sB + (kt & 1) * BSTAGE;

        #pragma unroll
        for (int ks = 0; ks < 2; ks++) {
            const int kk = ks * 16;
            uint32_t a[2][4];
            #pragma unroll
            for (int fm = 0; fm < 2; fm++) {
                int row = wm * 32 + fm * 16 + (lane & 15);
                uint32_t addr = aBase + (uint32_t)(row * APAD + kk + (lane >> 4) * 8) * 2u;
                ldsm4(a[fm][0], a[fm][1], a[fm][2], a[fm][3], addr);
            }
            uint32_t b[4][2];
            #pragma unroll
            for (int fn2 = 0; fn2 < 2; fn2++) {
                int krow = kk + (lane & 15);
                int ncol = wn * 32 + fn2 * 16 + (lane >> 4) * 8;
                uint32_t addr = bBase + (uint32_t)(krow * BPAD + ncol) * 2u;
                uint32_t r0, r1, r2, r3;
                ldsm4t(r0, r1, r2, r3, addr);
                b[fn2 * 2][0] = r0;     b[fn2 * 2][1] = r1;
                b[fn2 * 2 + 1][0] = r2; b[fn2 * 2 + 1][1] = r3;
            }
            #pragma unroll
            for (int fm = 0; fm < 2; fm++)
                #pragma unroll
                for (int fn = 0; fn < 4; fn++)
                    mma_bf16(acc[fm][fn], a[fm], b[fn]);
        }
        __syncthreads();
    }

    // ---- epilogue: bias + relu, bf16 pair stores ----
    #pragma unroll
    for (int fm = 0; fm < 2; fm++) {
        int row0 = bm + wm * 32 + fm * 16 + g;
        #pragma unroll
        for (int fn = 0; fn < 4; fn++) {
            int col0 = bn + wn * 32 + fn * 8 + 2 * t;
            float bv0 = bias[col0], bv1 = bias[col0 + 1];
            float v0 = acc[fm][fn][0] + bv0;
            float v1 = acc[fm][fn][1] + bv1;
            float v2 = acc[fm][fn][2] + bv0;
            float v3 = acc[fm][fn][3] + bv1;
            if (do_relu) {
                v0 = fmaxf(v0, 0.f); v1 = fmaxf(v1, 0.f);
                v2 = fmaxf(v2, 0.f); v3 = fmaxf(v3, 0.f);
            }
            *(uint32_t*)&C[(size_t)row0 * ldc + col0]       = pack_bf16(v0, v1);
            *(uint32_t*)&C[(size_t)(row0 + 8) * ldc + col0] = pack_bf16(v2, v3);
        }
    }
    #undef PREFETCH
}

// ---------------- interaction via tensor cores: per-batch E @ E^T ----------------
// 4 warps/block, one batch per warp. E = 32(27)x128 bf16 in smem; A and B frags
// come from the same ldsm.x4 loads (B-frag remap for N-rows-x-K-cols layout).
#define IW 4
__global__ __launch_bounds__(128) void interact_mma(const bf16* __restrict__ allb,
                                                    bf16* __restrict__ feat)
{
    __shared__ alignas(16) unsigned short E[IW][32][136];
    int warp = threadIdx.x >> 5;
    int lane = threadIdx.x & 31;
    int b = blockIdx.x * IW + warp;

    const bf16* src = allb + (size_t)b * NE_ * D_;
    // load 27 rows x 128 cols (16B chunks)
    for (int i = lane; i < 27 * 16; i += 32) {
        int r = i >> 4, c8 = (i & 15) * 8;
        *(uint4*)&E[warp][r][c8] = *(const uint4*)(src + r * 128 + c8);
    }
    __syncwarp();

    uint32_t base = (uint32_t)__cvta_generic_to_shared(&E[warp][0][0]);
    float acc[2][4][4];
    #pragma unroll
    for (int i = 0; i < 2; i++)
        #pragma unroll
        for (int j = 0; j < 4; j++)
            #pragma unroll
            for (int q = 0; q < 4; q++) acc[i][j][q] = 0.f;

    #pragma unroll
    for (int ks = 0; ks < 8; ks++) {
        const int kk = ks * 16;
        uint32_t a[2][4];
        #pragma unroll
        for (int fm = 0; fm < 2; fm++) {
            int row = fm * 16 + (lane & 15);
            uint32_t addr = base + (uint32_t)(row * 136 + kk + (lane >> 4) * 8) * 2u;
            ldsm4(a[fm][0], a[fm][1], a[fm][2], a[fm][3], addr);
        }
        // B fragments from the same registers: tile h rows 0-7 -> {m0,m2}, 8-15 -> {m1,m3}
        uint32_t bf[4][2];
        #pragma unroll
        for (int h = 0; h < 2; h++) {
            bf[h * 2][0]     = a[h][0]; bf[h * 2][1]     = a[h][2];
            bf[h * 2 + 1][0] = a[h][1]; bf[h * 2 + 1][1] = a[h][3];
        }
        #pragma unroll
        for (int fm = 0; fm < 2; fm++)
            #pragma unroll
            for (int fn = 0; fn < 4; fn++)
                mma_bf16(acc[fm][fn], a[fm], bf[fn]);
    }

    bf16* out = feat + (size_t)b * NFEATP;
    // dense copy: row 0 of E (from gmem) -> feat[0:128]
    *(uint2*)&out[lane * 4] = *(const uint2*)(src + lane * 4);
    if (lane == 0) out[NFEAT] = __float2bfloat16(0.f);   // pad col 479

    // scatter upper triangle (r < c < 27)
    #pragma unroll
    for (int fm = 0; fm < 2; fm++) {
        int r0 = fm * 16 + (lane >> 2);
        #pragma unroll
        for (int fn = 0; fn < 4; fn++) {
            int c0 = fn * 8 + 2 * (lane & 3);
            float v[4] = {acc[fm][fn][0], acc[fm][fn][1], acc[fm][fn][2], acc[fm][fn][3]};
            #pragma unroll
            for (int q = 0; q < 4; q++) {
                int r = r0 + (q >> 1) * 8;
                int c = c0 + (q & 1);
                if (r < NE_ && c < NE_ && c > r) {
                    int idx = r * NS_ - (r * (r - 1)) / 2 + (c - r - 1);
                    out[D_ + idx] = __float2bfloat16(v[q]);
                }
            }
        }
    }
}

// ---------------- final layer: sigmoid(t2 @ tw3 + tb3) ----------------
__global__ void final_kernel(const bf16* __restrict__ t2,
                             const float* __restrict__ w,
                             const float* __restrict__ bias,
                             float* __restrict__ out)
{
    int row = blockIdx.x * (blockDim.x >> 5) + (threadIdx.x >> 5);
    int lane = threadIdx.x & 31;
    if (row >= B_) return;
    const bf16* x = t2 + (size_t)row * 256;
    float s = 0.f;
    #pragma unroll
    for (int i = lane; i < 256; i += 32) s += __bfloat162float(x[i]) * w[i];
    #pragma unroll
    for (int o = 16; o; o >>= 1) s += __shfl_xor_sync(0xFFFFFFFFu, s, o);
    if (lane == 0) out[row] = 1.f / (1.f + expf(-(s + bias[0])));
}

// ---------------- launch ----------------
extern "C" void kernel_launch(void* const* d_in, const int* in_sizes, int n_in,
                              void* d_out, int out_size)
{
    const float* dense_x   = (const float*)d_in[0];
    const void*  sparse_x  = d_in[1];
    const void*  sparse_of = d_in[2];
    const float* tables    = (const float*)d_in[3];
    const float* bw1 = (const float*)d_in[4];
    const float* bb1 = (const float*)d_in[5];
    const float* bw2 = (const float*)d_in[6];
    const float* bb2 = (const float*)d_in[7];
    const float* bw3 = (const float*)d_in[8];
    const float* bb3 = (const float*)d_in[9];
    const float* tw1 = (const float*)d_in[10];
    const float* tb1 = (const float*)d_in[11];
    const float* tw2 = (const float*)d_in[12];
    const float* tb2 = (const float*)d_in[13];
    const float* tw3 = (const float*)d_in[14];
    const float* tb3 = (const float*)d_in[15];
    float* out = (float*)d_out;

    bf16 *h1b, *h2b, *allb, *featb, *t1b, *t2b, *wb2, *wb3, *wt1, *wt2;
    cudaGetSymbolAddress((void**)&h1b,   g_h1b);
    cudaGetSymbolAddress((void**)&h2b,   g_h2b);
    cudaGetSymbolAddress((void**)&allb,  g_allb);
    cudaGetSymbolAddress((void**)&featb, g_featb);
    cudaGetSymbolAddress((void**)&t1b,   g_t1b);
    cudaGetSymbolAddress((void**)&t2b,   g_t2b);
    cudaGetSymbolAddress((void**)&wb2,   g_wb2);
    cudaGetSymbolAddress((void**)&wb3,   g_wb3);
    cudaGetSymbolAddress((void**)&wt1,   g_wt1);
    cudaGetSymbolAddress((void**)&wt2,   g_wt2);

    // weight conversion (small)
    prep_weights<<<1024, 256>>>(bw2, bw3, tw1, tw2);

    // embedding bags -> allb slots [1..26]
    {
        int nwarps = B_ * NS_;
        int blocks = (nwarps * 32 + 255) / 256;
        embed_kernel<<<blocks, 256>>>(sparse_x, sparse_of, tables);
    }

    // bottom MLP
    layer1_kernel<<<B_ / 16, 256>>>(dense_x, bw1, bb1);                               // -> h1b
    gemm_bf16a<<<dim3(256 / TBN, B_ / TBM), 256>>>(h1b, wb2, bb2, h2b, 256, 512, 512, 256, 1);
    gemm_bf16a<<<dim3(128 / TBN, B_ / TBM), 256>>>(h2b, wb3, bb3, allb, 128, 256, 256, NE_ * D_, 1);

    // interaction (tensor cores) -> featb
    interact_mma<<<B_ / IW, 128>>>(allb, featb);

    // top MLP
    gemm_bf16a<<<dim3(512 / TBN, B_ / TBM), 256>>>(featb, wt1, tb1, t1b, 512, 480, NFEATP, 512, 1);
    gemm_bf16a<<<dim3(256 / TBN, B_ / TBM), 256>>>(t1b, wt2, tb2, t2b, 256, 512, 512, 256, 1);

    // final sigmoid layer
    final_kernel<<<B_ / 8, 256>>>(t2b, tw3, tb3, out);
}

// round 5
// speedup vs baseline: 3.2950x; 1.0705x over previous
#include <cuda_runtime.h>
#include <cuda_bf16.h>
#include <math.h>
#include <stdint.h>

// Problem constants
#define B_   8192
#define P_   4
#define L_   (B_ * P_)
#define V_   100000
#define D_   128
#define NS_  26
#define NE_  (NS_ + 1)
#define NINT ((NE_ * (NE_ - 1)) / 2)   // 351
#define NFEAT (D_ + NINT)              // 479
#define NFEATP 480

typedef __nv_bfloat16 bf16;

// ---------------- scratch ----------------
__device__ bf16 g_h1b[(size_t)B_ * 512];
__device__ bf16 g_h2b[(size_t)B_ * 256];
__device__ bf16 g_allb[(size_t)B_ * NE_ * D_];
__device__ bf16 g_featb[(size_t)B_ * NFEATP];
__device__ bf16 g_t1b[(size_t)B_ * 512];
__device__ bf16 g_t2b[(size_t)B_ * 256];
__device__ bf16 g_wb2[512 * 256];
__device__ bf16 g_wb3[256 * 128];
__device__ bf16 g_wt1[480 * 512];   // row 479 zeroed
__device__ bf16 g_wt2[512 * 256];

// ---------------- helpers ----------------
__device__ __forceinline__ uint32_t pack_bf16(float a, float b) {
    __nv_bfloat162 h = __floats2bfloat162_rn(a, b);
    return *reinterpret_cast<uint32_t*>(&h);
}
__device__ __forceinline__ void ldsm4(uint32_t& r0, uint32_t& r1, uint32_t& r2, uint32_t& r3,
                                      uint32_t saddr) {
    asm volatile("ldmatrix.sync.aligned.m8n8.x4.shared.b16 {%0,%1,%2,%3}, [%4];"
                 : "=r"(r0), "=r"(r1), "=r"(r2), "=r"(r3) : "r"(saddr));
}
__device__ __forceinline__ void ldsm4t(uint32_t& r0, uint32_t& r1, uint32_t& r2, uint32_t& r3,
                                       uint32_t saddr) {
    asm volatile("ldmatrix.sync.aligned.m8n8.x4.trans.shared.b16 {%0,%1,%2,%3}, [%4];"
                 : "=r"(r0), "=r"(r1), "=r"(r2), "=r"(r3) : "r"(saddr));
}
__device__ __forceinline__ void mma_bf16(float* c, const uint32_t* a, const uint32_t* b) {
    asm volatile(
        "mma.sync.aligned.m16n8k16.row.col.f32.bf16.bf16.f32 "
        "{%0,%1,%2,%3},{%4,%5,%6,%7},{%8,%9},{%0,%1,%2,%3};"
        : "+f"(c[0]), "+f"(c[1]), "+f"(c[2]), "+f"(c[3])
        : "r"(a[0]), "r"(a[1]), "r"(a[2]), "r"(a[3]), "r"(b[0]), "r"(b[1]));
}
__device__ __forceinline__ void cpasync16(uint32_t dst, const void* src) {
    asm volatile("cp.async.cg.shared.global [%0], [%1], 16;" :: "r"(dst), "l"(src));
}

// ---------------- weight prep ----------------
__global__ void prep_weights(const float* __restrict__ bw2, const float* __restrict__ bw3,
                             const float* __restrict__ tw1, const float* __restrict__ tw2)
{
    const int S0 = 512 * 256;
    const int S1 = S0 + 256 * 128;
    const int S2 = S1 + 480 * 512;
    const int S3 = S2 + 512 * 256;
    for (int i = blockIdx.x * blockDim.x + threadIdx.x; i < S3; i += gridDim.x * blockDim.x) {
        if (i < S0) {
            g_wb2[i] = __float2bfloat16(bw2[i]);
        } else if (i < S1) {
            int j = i - S0;
            g_wb3[j] = __float2bfloat16(bw3[j]);
        } else if (i < S2) {
            int j = i - S1;
            int k = j >> 9;
            g_wt1[j] = (k < NFEAT) ? __float2bfloat16(tw1[j]) : __float2bfloat16(0.f);
        } else {
            int j = i - S2;
            g_wt2[j] = __float2bfloat16(tw2[j]);
        }
    }
}

// ---------------- embedding bag -> bf16, unrolled size-4 fast path ----------------
__global__ void embed_kernel(const void* __restrict__ sx_raw,
                             const void* __restrict__ off_raw,
                             const float* __restrict__ tables)
{
    int g = blockIdx.x * blockDim.x + threadIdx.x;
    int warp = g >> 5;
    int lane = g & 31;
    if (warp >= B_ * NS_) return;
    int b = warp / NS_;
    int s = warp - b * NS_;

    const long long* off64 = (const long long*)off_raw;
    const int*       off32 = (const int*)off_raw;
    bool is64 = (off64[1] == (long long)P_);

    long long start, end;
    if (is64) {
        start = off64[b];
        end   = (b + 1 < B_) ? off64[b + 1] : (long long)L_;
    } else {
        start = (long long)off32[b];
        end   = (b + 1 < B_) ? (long long)off32[b + 1] : (long long)L_;
    }

    const long long* sx64 = (const long long*)sx_raw;
    const int*       sx32 = (const int*)sx_raw;
    const float* tb = tables + (size_t)s * V_ * D_;

    float4 acc = make_float4(0.f, 0.f, 0.f, 0.f);
    int cnt = (int)(end - start);
    if (cnt == 4) {
        long long i0, i1, i2, i3;
        if (is64) {
            i0 = sx64[(start + 0) * NS_ + s]; i1 = sx64[(start + 1) * NS_ + s];
            i2 = sx64[(start + 2) * NS_ + s]; i3 = sx64[(start + 3) * NS_ + s];
        } else {
            i0 = sx32[(start + 0) * NS_ + s]; i1 = sx32[(start + 1) * NS_ + s];
            i2 = sx32[(start + 2) * NS_ + s]; i3 = sx32[(start + 3) * NS_ + s];
        }
        float4 v0 = __ldg((const float4*)(tb + (size_t)i0 * D_) + lane);
        float4 v1 = __ldg((const float4*)(tb + (size_t)i1 * D_) + lane);
        float4 v2 = __ldg((const float4*)(tb + (size_t)i2 * D_) + lane);
        float4 v3 = __ldg((const float4*)(tb + (size_t)i3 * D_) + lane);
        acc.x = (v0.x + v1.x) + (v2.x + v3.x);
        acc.y = (v0.y + v1.y) + (v2.y + v3.y);
        acc.z = (v0.z + v1.z) + (v2.z + v3.z);
        acc.w = (v0.w + v1.w) + (v2.w + v3.w);
    } else {
        for (long long p = start; p < end; ++p) {
            long long idx = is64 ? sx64[p * NS_ + s] : (long long)sx32[p * NS_ + s];
            float4 v = __ldg((const float4*)(tb + (size_t)idx * D_) + lane);
            acc.x += v.x; acc.y += v.y; acc.z += v.z; acc.w += v.w;
        }
    }
    uint2 val;
    val.x = pack_bf16(acc.x, acc.y);
    val.y = pack_bf16(acc.z, acc.w);
    *(uint2*)&g_allb[((size_t)b * NE_ + 1 + s) * D_ + lane * 4] = val;
}

// ---------------- layer1: dense_x(13) -> 512 ----------------
__global__ __launch_bounds__(256) void layer1_kernel(const float* __restrict__ X,
                                                     const float* __restrict__ W,
                                                     const float* __restrict__ bias)
{
    __shared__ float As[16][13];
    int m0 = blockIdx.x * 16;
    int tid = threadIdx.x;
    if (tid < 16 * 13) As[tid / 13][tid % 13] = X[(size_t)(m0 + tid / 13) * 13 + tid % 13];
    __syncthreads();

    int n0 = tid * 2;
    float w0[13], w1[13];
    #pragma unroll
    for (int k = 0; k < 13; k++) {
        w0[k] = W[k * 512 + n0];
        w1[k] = W[k * 512 + n0 + 1];
    }
    float b0 = bias[n0], b1 = bias[n0 + 1];
    #pragma unroll 4
    for (int r = 0; r < 16; r++) {
        float s0 = b0, s1 = b1;
        #pragma unroll
        for (int k = 0; k < 13; k++) {
            float a = As[r][k];
            s0 += a * w0[k];
            s1 += a * w1[k];
        }
        s0 = fmaxf(s0, 0.f); s1 = fmaxf(s1, 0.f);
        *(uint32_t*)&g_h1b[(size_t)(m0 + r) * 512 + n0] = pack_bf16(s0, s1);
    }
}

// ---------------- templated bf16 GEMM, 3-stage cp.async pipeline ----------------
// BN: block n-tile (64 or 128). WMW: warps along m. MF: m-frags per warp.
// Warp layout: wm = warp % WMW, wn = warp / WMW; warp tile (16*MF) x 32.
// M % 128 == 0, K % 32 == 0.
#define APAD 40

template<int BN, int WMW, int MF>
__global__ __launch_bounds__(256) void gemm_bf16p(
    const bf16* __restrict__ A,
    const bf16* __restrict__ Wt,
    const float* __restrict__ bias,
    bf16* __restrict__ C,
    int N, int K, int lda, int ldc, int do_relu)
{
    constexpr int BPAD = BN + 8;
    constexpr int CB   = BN / 8;       // 16B chunks per B row
    constexpr int WMT  = 16 * MF;      // warp m tile

    extern __shared__ unsigned short sm[];
    unsigned short* Asm = sm;                          // [3][128][APAD]
    unsigned short* Bsm = sm + 3 * 128 * APAD;         // [3][32][BPAD]

    const int tid  = threadIdx.x;
    const int warp = tid >> 5;
    const int lane = tid & 31;
    const int wm   = warp % WMW;
    const int wn   = warp / WMW;
    const int g    = lane >> 2;
    const int t    = lane & 3;

    const int bm = blockIdx.y * 128;
    const int bn = blockIdx.x * BN;

    uint32_t sA = (uint32_t)__cvta_generic_to_shared(Asm);
    uint32_t sB = (uint32_t)__cvta_generic_to_shared(Bsm);
    const uint32_t ASTG = 128 * APAD * 2;
    const uint32_t BSTG = 32 * BPAD * 2;

    float acc[MF][4][4];
    #pragma unroll
    for (int i = 0; i < MF; i++)
        #pragma unroll
        for (int j = 0; j < 4; j++)
            #pragma unroll
            for (int q = 0; q < 4; q++) acc[i][j][q] = 0.f;

    const int nk = K / 32;

    auto prefetch = [&](int kt, int buf) {
        int k0 = kt * 32;
        #pragma unroll
        for (int c = tid; c < 512; c += 256) {
            int r = c >> 2, c8 = (c & 3) * 8;
            cpasync16(sA + buf * ASTG + (uint32_t)(r * APAD + c8) * 2,
                      A + (size_t)(bm + r) * lda + k0 + c8);
        }
        #pragma unroll
        for (int c = tid; c < 32 * CB; c += 256) {
            int r = c / CB, c8 = (c % CB) * 8;
            cpasync16(sB + buf * BSTG + (uint32_t)(r * BPAD + c8) * 2,
                      Wt + (size_t)(k0 + r) * N + bn + c8);
        }
        asm volatile("cp.async.commit_group;" ::: "memory");
    };

    prefetch(0, 0);
    prefetch(1, 1);

    for (int kt = 0; kt < nk; kt++) {
        asm volatile("cp.async.wait_group 1;" ::: "memory");
        __syncthreads();
        if (kt + 2 < nk) prefetch(kt + 2, (kt + 2) % 3);
        else asm volatile("cp.async.commit_group;" ::: "memory");  // keep group count aligned

        uint32_t aBase = sA + (uint32_t)(kt % 3) * ASTG;
        uint32_t bBase = sB + (uint32_t)(kt % 3) * BSTG;

        #pragma unroll
        for (int ks = 0; ks < 2; ks++) {
            const int kk = ks * 16;
            uint32_t a[MF][4];
            #pragma unroll
            for (int fm = 0; fm < MF; fm++) {
                int row = wm * WMT + fm * 16 + (lane & 15);
                uint32_t addr = aBase + (uint32_t)(row * APAD + kk + (lane >> 4) * 8) * 2u;
                ldsm4(a[fm][0], a[fm][1], a[fm][2], a[fm][3], addr);
            }
            uint32_t b[4][2];
            #pragma unroll
            for (int fn2 = 0; fn2 < 2; fn2++) {
                int krow = kk + (lane & 15);
                int ncol = wn * 32 + fn2 * 16 + (lane >> 4) * 8;
                uint32_t addr = bBase + (uint32_t)(krow * BPAD + ncol) * 2u;
                uint32_t r0, r1, r2, r3;
                ldsm4t(r0, r1, r2, r3, addr);
                b[fn2 * 2][0] = r0;     b[fn2 * 2][1] = r1;
                b[fn2 * 2 + 1][0] = r2; b[fn2 * 2 + 1][1] = r3;
            }
            #pragma unroll
            for (int fm = 0; fm < MF; fm++)
                #pragma unroll
                for (int fn = 0; fn < 4; fn++)
                    mma_bf16(acc[fm][fn], a[fm], b[fn]);
        }
    }

    // epilogue
    #pragma unroll
    for (int fm = 0; fm < MF; fm++) {
        int row0 = bm + wm * WMT + fm * 16 + g;
        #pragma unroll
        for (int fn = 0; fn < 4; fn++) {
            int col0 = bn + wn * 32 + fn * 8 + 2 * t;
            float bv0 = bias[col0], bv1 = bias[col0 + 1];
            float v0 = acc[fm][fn][0] + bv0;
            float v1 = acc[fm][fn][1] + bv1;
            float v2 = acc[fm][fn][2] + bv0;
            float v3 = acc[fm][fn][3] + bv1;
            if (do_relu) {
                v0 = fmaxf(v0, 0.f); v1 = fmaxf(v1, 0.f);
                v2 = fmaxf(v2, 0.f); v3 = fmaxf(v3, 0.f);
            }
            *(uint32_t*)&C[(size_t)row0 * ldc + col0]       = pack_bf16(v0, v1);
            *(uint32_t*)&C[(size_t)(row0 + 8) * ldc + col0] = pack_bf16(v2, v3);
        }
    }
}

// ---------------- interaction via tensor cores ----------------
#define IW 4
__global__ __launch_bounds__(128) void interact_mma(const bf16* __restrict__ allb,
                                                    bf16* __restrict__ feat)
{
    __shared__ alignas(16) unsigned short E[IW][32][136];
    int warp = threadIdx.x >> 5;
    int lane = threadIdx.x & 31;
    int b = blockIdx.x * IW + warp;

    const bf16* src = allb + (size_t)b * NE_ * D_;
    for (int i = lane; i < 27 * 16; i += 32) {
        int r = i >> 4, c8 = (i & 15) * 8;
        *(uint4*)&E[warp][r][c8] = *(const uint4*)(src + r * 128 + c8);
    }
    __syncwarp();

    uint32_t base = (uint32_t)__cvta_generic_to_shared(&E[warp][0][0]);
    float acc[2][4][4];
    #pragma unroll
    for (int i = 0; i < 2; i++)
        #pragma unroll
        for (int j = 0; j < 4; j++)
            #pragma unroll
            for (int q = 0; q < 4; q++) acc[i][j][q] = 0.f;

    #pragma unroll
    for (int ks = 0; ks < 8; ks++) {
        const int kk = ks * 16;
        uint32_t a[2][4];
        #pragma unroll
        for (int fm = 0; fm < 2; fm++) {
            int row = fm * 16 + (lane & 15);
            uint32_t addr = base + (uint32_t)(row * 136 + kk + (lane >> 4) * 8) * 2u;
            ldsm4(a[fm][0], a[fm][1], a[fm][2], a[fm][3], addr);
        }
        uint32_t bf[4][2];
        #pragma unroll
        for (int h = 0; h < 2; h++) {
            bf[h * 2][0]     = a[h][0]; bf[h * 2][1]     = a[h][2];
            bf[h * 2 + 1][0] = a[h][1]; bf[h * 2 + 1][1] = a[h][3];
        }
        #pragma unroll
        for (int fm = 0; fm < 2; fm++)
            #pragma unroll
            for (int fn = 0; fn < 4; fn++)
                mma_bf16(acc[fm][fn], a[fm], bf[fn]);
    }

    bf16* out = feat + (size_t)b * NFEATP;
    *(uint2*)&out[lane * 4] = *(const uint2*)(src + lane * 4);
    if (lane == 0) out[NFEAT] = __float2bfloat16(0.f);

    #pragma unroll
    for (int fm = 0; fm < 2; fm++) {
        int r0 = fm * 16 + (lane >> 2);
        #pragma unroll
        for (int fn = 0; fn < 4; fn++) {
            int c0 = fn * 8 + 2 * (lane & 3);
            float v[4] = {acc[fm][fn][0], acc[fm][fn][1], acc[fm][fn][2], acc[fm][fn][3]};
            #pragma unroll
            for (int q = 0; q < 4; q++) {
                int r = r0 + (q >> 1) * 8;
                int c = c0 + (q & 1);
                if (r < NE_ && c < NE_ && c > r) {
                    int idx = r * NS_ - (r * (r - 1)) / 2 + (c - r - 1);
                    out[D_ + idx] = __float2bfloat16(v[q]);
                }
            }
        }
    }
}

// ---------------- final layer ----------------
__global__ void final_kernel(const bf16* __restrict__ t2,
                             const float* __restrict__ w,
                             const float* __restrict__ bias,
                             float* __restrict__ out)
{
    int row = blockIdx.x * (blockDim.x >> 5) + (threadIdx.x >> 5);
    int lane = threadIdx.x & 31;
    if (row >= B_) return;
    const bf16* x = t2 + (size_t)row * 256;
    float s = 0.f;
    #pragma unroll
    for (int i = lane; i < 256; i += 32) s += __bfloat162float(x[i]) * w[i];
    #pragma unroll
    for (int o = 16; o; o >>= 1) s += __shfl_xor_sync(0xFFFFFFFFu, s, o);
    if (lane == 0) out[row] = 1.f / (1.f + expf(-(s + bias[0])));
}

// ---------------- launch ----------------
extern "C" void kernel_launch(void* const* d_in, const int* in_sizes, int n_in,
                              void* d_out, int out_size)
{
    const float* dense_x   = (const float*)d_in[0];
    const void*  sparse_x  = d_in[1];
    const void*  sparse_of = d_in[2];
    const float* tables    = (const float*)d_in[3];
    const float* bw1 = (const float*)d_in[4];
    const float* bb1 = (const float*)d_in[5];
    const float* bw2 = (const float*)d_in[6];
    const float* bb2 = (const float*)d_in[7];
    const float* bw3 = (const float*)d_in[8];
    const float* bb3 = (const float*)d_in[9];
    const float* tw1 = (const float*)d_in[10];
    const float* tb1 = (const float*)d_in[11];
    const float* tw2 = (const float*)d_in[12];
    const float* tb2 = (const float*)d_in[13];
    const float* tw3 = (const float*)d_in[14];
    const float* tb3 = (const float*)d_in[15];
    float* out = (float*)d_out;

    bf16 *h1b, *h2b, *allb, *featb, *t1b, *t2b, *wb2, *wb3, *wt1, *wt2;
    cudaGetSymbolAddress((void**)&h1b,   g_h1b);
    cudaGetSymbolAddress((void**)&h2b,   g_h2b);
    cudaGetSymbolAddress((void**)&allb,  g_allb);
    cudaGetSymbolAddress((void**)&featb, g_featb);
    cudaGetSymbolAddress((void**)&t1b,   g_t1b);
    cudaGetSymbolAddress((void**)&t2b,   g_t2b);
    cudaGetSymbolAddress((void**)&wb2,   g_wb2);
    cudaGetSymbolAddress((void**)&wb3,   g_wb3);
    cudaGetSymbolAddress((void**)&wt1,   g_wt1);
    cudaGetSymbolAddress((void**)&wt2,   g_wt2);

    constexpr int SM64  = 3 * (128 * APAD + 32 * 72)  * 2;   // 44544 B
    constexpr int SM128 = 3 * (128 * APAD + 32 * 136) * 2;   // 56832 B
    cudaFuncSetAttribute(gemm_bf16p<64, 4, 2>,  cudaFuncAttributeMaxDynamicSharedMemorySize, SM64);
    cudaFuncSetAttribute(gemm_bf16p<128, 2, 4>, cudaFuncAttributeMaxDynamicSharedMemorySize, SM128);

    prep_weights<<<1024, 256>>>(bw2, bw3, tw1, tw2);

    {
        int nwarps = B_ * NS_;
        int blocks = (nwarps * 32 + 255) / 256;
        embed_kernel<<<blocks, 256>>>(sparse_x, sparse_of, tables);
    }

    // bottom MLP
    layer1_kernel<<<B_ / 16, 256>>>(dense_x, bw1, bb1);
    gemm_bf16p<64, 4, 2><<<dim3(4, 64), 256, SM64>>>(h1b, wb2, bb2, h2b, 256, 512, 512, 256, 1);
    gemm_bf16p<64, 4, 2><<<dim3(2, 64), 256, SM64>>>(h2b, wb3, bb3, allb, 128, 256, 256, NE_ * D_, 1);

    // interaction
    interact_mma<<<B_ / IW, 128>>>(allb, featb);

    // top MLP
    gemm_bf16p<128, 2, 4><<<dim3(4, 64), 256, SM128>>>(featb, wt1, tb1, t1b, 512, 480, NFEATP, 512, 1);
    gemm_bf16p<64, 4, 2><<<dim3(4, 64), 256, SM64>>>(t1b, wt2, tb2, t2b, 256, 512, 512, 256, 1);

    // final sigmoid
    final_kernel<<<B_ / 8, 256>>>(t2b, tw3, tb3, out);
}